// round 2
// baseline (speedup 1.0000x reference)
#include <cuda_runtime.h>
#include <cstdint>
#include <cstddef>

// Problem constants
#define D        256          // embedding dim
#define K        1024         // num embeddings
#define HW       1024         // 32*32 spatial per image
#define NPOS     32768        // 32 * HW positions
#define OUT_ELEMS 8388608     // NPOS * D

// Tiling
#define TP       128          // positions per block
#define KC       64           // codes per chunk
#define NCHUNKS  (K / KC)     // 16
#define DPAIRS   (D / 2)      // 128
#define NTHREADS 256
#define WROW     (D + 2)      // padded Ws row (floats) -> 1032B row stride (8B-aligned)
#define NBLOCKS  (NPOS / TP)  // 256

#define SMEM_FLOATS (D*TP + KC*WROW + KC)   // Xs + Ws + whalf = 49344 floats = 197376 B

__device__ float g_wsq[K];           // 0.5 * ||w_k||^2
__device__ float g_partial[NBLOCKS]; // per-block loss partial sums

// ---- packed fp32x2 helpers (FFMA2 path: 2x fp32 FMA rate on sm_10x) ----
__device__ __forceinline__ unsigned long long ffma2(unsigned long long a,
                                                    unsigned long long b,
                                                    unsigned long long c) {
    unsigned long long d;
    asm("fma.rn.f32x2 %0, %1, %2, %3;" : "=l"(d) : "l"(a), "l"(b), "l"(c));
    return d;
}
__device__ __forceinline__ unsigned long long pack2(float lo, float hi) {
    unsigned long long d;
    asm("mov.b64 %0, {%1, %2};" : "=l"(d) : "f"(lo), "f"(hi));
    return d;
}
__device__ __forceinline__ float2 unpack2(unsigned long long v) {
    float2 r;
    asm("mov.b64 {%0, %1}, %2;" : "=f"(r.x), "=f"(r.y) : "l"(v));
    return r;
}

// ---- precompute 0.5*||w_k||^2 ----
__global__ void vq_wsq(const float* __restrict__ wgt)
{
    int k = blockIdx.x * blockDim.x + threadIdx.x;
    if (k < K) {
        const float* r = wgt + (size_t)k * D;
        float s = 0.f;
        #pragma unroll 8
        for (int j = 0; j < D; ++j) { float w = r[j]; s = fmaf(w, w, s); }
        g_wsq[k] = 0.5f * s;
    }
}

// ---- main fused kernel: scores + argmax + gather + NCHW write + loss partials ----
// argmin_k ||x-w_k||^2 == argmax_k (x.w_k - 0.5||w_k||^2); ||x||^2 dropped.
// Forward value of straight-through output is exactly the gathered codebook row.
// loss = codebook + 0.25*commit = 1.25 * mean((q-x)^2).
__global__ void __launch_bounds__(NTHREADS, 1)
vq_main(const float* __restrict__ inp, const float* __restrict__ wgt,
        float* __restrict__ out)
{
    extern __shared__ float smem[];
    float* Xs    = smem;               // [D][TP]   (d-major: matches NCHW loads)
    float* Ws    = smem + D * TP;      // [KC][WROW] k-major, padded
    float* whalf = Ws + KC * WROW;     // [KC]
    // aliases into Ws region (valid only after last chunk's compute):
    float* redv  = Ws;                   // [TP][16]
    int*   redi  = (int*)(Ws + TP * 16); // [TP][16]
    int*   sidx  = (int*)(Ws + TP * 32); // [TP]

    const int tid = threadIdx.x;
    const int tp  = tid & 15;          // 16 position-groups (8 positions each)
    const int tk  = tid >> 4;          // 16 code-groups (4 codes each)

    const int n0  = blockIdx.x * TP;   // block's first global position
    const int b   = n0 >> 10;          // image index (TP divides HW)
    const int hw0 = n0 & 1023;

    // ---- load X tile: Xs[d][p], coalesced global float4 over positions ----
    {
        const float* src = inp + (((size_t)b * D) << 10) + hw0;
        #pragma unroll
        for (int it = 0; it < (D * TP / 4) / NTHREADS; ++it) {
            int idx = tid + it * NTHREADS;
            int d   = idx >> 5;            // 32 float4 per d-row
            int pq  = (idx & 31) << 2;
            float4 v = *(const float4*)(src + (((size_t)d) << 10) + pq);
            *(float4*)&Xs[d * TP + pq] = v;
        }
    }

    unsigned long long acc[8][4];
    float bestv[8];
    int   besti[8];
    #pragma unroll
    for (int i = 0; i < 8; ++i) { bestv[i] = -1e30f; besti[i] = 0; }
    #pragma unroll
    for (int i = 0; i < 8; ++i)
        #pragma unroll
        for (int j = 0; j < 4; ++j) acc[i][j] = 0ull;

    for (int c = 0; c < NCHUNKS; ++c) {
        const int kc = c * KC;
        __syncthreads();   // prev chunk compute done (also covers initial Xs fill)

        // load W chunk: coalesced float4 reads, store to padded rows
        #pragma unroll
        for (int it = 0; it < (KC * D / 4) / NTHREADS; ++it) {
            int idx = tid + it * NTHREADS;
            int k   = idx >> 6;            // 64 float4 per code row
            int c4  = (idx & 63) << 2;
            float4 v = *(const float4*)&wgt[(size_t)(kc + k) * D + c4];
            float* dst = &Ws[k * WROW + c4];
            *(float2*)(dst)     = make_float2(v.x, v.y);
            *(float2*)(dst + 2) = make_float2(v.z, v.w);
        }
        if (tid < KC) whalf[tid] = g_wsq[kc + tid];
        __syncthreads();

        const float* xb = &Xs[tp * 8];
        const float* wb = &Ws[(tk * 4) * WROW];

        #pragma unroll 2
        for (int dp = 0; dp < DPAIRS; ++dp) {
            const float* x0 = xb + (2 * dp) * TP;
            float4 a0 = *(const float4*)(x0);
            float4 a1 = *(const float4*)(x0 + 4);
            float4 b0 = *(const float4*)(x0 + TP);
            float4 b1 = *(const float4*)(x0 + TP + 4);
            unsigned long long xp[8];
            xp[0] = pack2(a0.x, b0.x); xp[1] = pack2(a0.y, b0.y);
            xp[2] = pack2(a0.z, b0.z); xp[3] = pack2(a0.w, b0.w);
            xp[4] = pack2(a1.x, b1.x); xp[5] = pack2(a1.y, b1.y);
            xp[6] = pack2(a1.z, b1.z); xp[7] = pack2(a1.w, b1.w);
            unsigned long long wp[4];
            #pragma unroll
            for (int j = 0; j < 4; ++j)   // the natural float2 IS the d-pair
                wp[j] = *(const unsigned long long*)(wb + j * WROW + 2 * dp);
            #pragma unroll
            for (int i = 0; i < 8; ++i)
                #pragma unroll
                for (int j = 0; j < 4; ++j)
                    acc[i][j] = ffma2(xp[i], wp[j], acc[i][j]);
        }

        // chunk scores: s = x.w - 0.5||w||^2 ; running max, strict > => lowest k wins
        float wh[4];
        #pragma unroll
        for (int j = 0; j < 4; ++j) wh[j] = whalf[tk * 4 + j];
        #pragma unroll
        for (int i = 0; i < 8; ++i) {
            #pragma unroll
            for (int j = 0; j < 4; ++j) {
                float2 s2 = unpack2(acc[i][j]);
                acc[i][j] = 0ull;
                float s = s2.x + s2.y - wh[j];
                if (s > bestv[i]) { bestv[i] = s; besti[i] = kc + tk * 4 + j; }
            }
        }
    }

    // ---- cross-thread argmax reduction (16 tk-threads per position) ----
    __syncthreads();   // Ws no longer needed; safe to alias
    #pragma unroll
    for (int i = 0; i < 8; ++i) {
        int p = tp * 8 + i;
        redv[p * 16 + tk] = bestv[i];
        redi[p * 16 + tk] = besti[i];
    }
    __syncthreads();
    if (tid < TP) {
        int p = tid;
        float bv = redv[p * 16];
        int   bi = redi[p * 16];
        #pragma unroll
        for (int t = 1; t < 16; ++t) {
            float v  = redv[p * 16 + t];
            int   ti = redi[p * 16 + t];
            if (v > bv || (v == bv && ti < bi)) { bv = v; bi = ti; }
        }
        sidx[p] = bi;
    }
    __syncthreads();

    // ---- epilogue: gather codebook row, write NCHW (coalesced over hw), loss ----
    {
        int p    = tid & (TP - 1);     // warp = 32 consecutive positions -> coalesced STG
        int dsel = tid >> 7;           // 0: even d, 1: odd d
        int myidx = sidx[p];
        const float* wrow = wgt + (size_t)myidx * D;
        float* op = out + (((size_t)b * D) << 10) + hw0 + p;
        float lsum = 0.f;
        #pragma unroll 4
        for (int d = dsel; d < D; d += 2) {
            float q  = __ldg(wrow + d);       // L2-resident gather (weights ~1MB)
            float x  = Xs[d * TP + p];
            float df = q - x;
            lsum = fmaf(df, df, lsum);
            op[((size_t)d) << 10] = q;
        }
        __syncthreads();
        float* sred = Ws;   // reuse (disjoint from sidx/Xs)
        sred[tid] = lsum;
        __syncthreads();
        #pragma unroll
        for (int s = NTHREADS / 2; s > 0; s >>= 1) {
            if (tid < s) sred[tid] += sred[tid + s];
            __syncthreads();
        }
        if (tid == 0) g_partial[blockIdx.x] = sred[0];
    }
}

// ---- final deterministic loss reduction: loss = 1.25 * mean((q-x)^2) ----
__global__ void vq_loss(float* __restrict__ out, int loss_index)
{
    __shared__ float s[NBLOCKS];
    int t = threadIdx.x;
    s[t] = g_partial[t];
    __syncthreads();
    for (int st = NBLOCKS / 2; st > 0; st >>= 1) {
        if (t < st) s[t] += s[t + st];
        __syncthreads();
    }
    if (t == 0) out[loss_index] = 1.25f * s[0] / (float)OUT_ELEMS;
}

extern "C" void kernel_launch(void* const* d_in, const int* in_sizes, int n_in,
                              void* d_out, int out_size)
{
    (void)in_sizes; (void)n_in;
    const float* inp = (const float*)d_in[0];   // [32,256,32,32] fp32 NCHW
    const float* wgt = (const float*)d_in[1];   // [1024,256] fp32
    float* out = (float*)d_out;                 // [32,256,32,32] fp32 + loss scalar

    size_t smem_bytes = (size_t)SMEM_FLOATS * sizeof(float);
    // Legal during stream capture (not a stream op). Idempotent; ignore status.
    (void)cudaFuncSetAttribute(vq_main, cudaFuncAttributeMaxDynamicSharedMemorySize,
                               (int)smem_bytes);

    vq_wsq <<<K / 128, 128>>>(wgt);
    vq_main<<<NBLOCKS, NTHREADS, smem_bytes>>>(inp, wgt, out);
    vq_loss<<<1, NBLOCKS>>>(out, out_size - 1);
}

// round 3
// speedup vs baseline: 1.5864x; 1.5864x over previous
#include <cuda_runtime.h>
#include <cstdint>
#include <cstddef>

#define D         256
#define K         1024
#define TP        128             // positions per block
#define KC        32              // codes per chunk
#define NCHUNKS   (K / KC)        // 32
#define NTHREADS  256
#define NBLOCKS   256             // 32768 / TP
#define OUT_ELEMS 8388608

// smem floats: Xs2 (D/2 * TP * 2 = 32768) + 2 W bufs (2*KC*D = 16384) + wsq (1024)
#define SMEM_FLOATS (32768 + 16384 + 1024)

__device__ float g_wsq[K];
__device__ float g_partial[NBLOCKS];
__device__ int   g_count;         // zero-init; self-resetting -> graph-replay safe

// ---- packed fp32x2 (FFMA2: 2x fp32 FMA rate, only reachable via PTX) ----
__device__ __forceinline__ unsigned long long ffma2(unsigned long long a,
                                                    unsigned long long b,
                                                    unsigned long long c) {
    unsigned long long d;
    asm("fma.rn.f32x2 %0, %1, %2, %3;" : "=l"(d) : "l"(a), "l"(b), "l"(c));
    return d;
}
__device__ __forceinline__ float2 unpack2(unsigned long long v) {
    float2 r;
    asm("mov.b64 {%0, %1}, %2;" : "=f"(r.x), "=f"(r.y) : "l"(v));
    return r;
}

// ---- 0.5*||w_k||^2 : warp per row ----
__global__ void vq_wsq(const float* __restrict__ wgt)
{
    int wid  = threadIdx.x >> 5;
    int lane = threadIdx.x & 31;
    int row  = blockIdx.x * 8 + wid;
    const float4* r = (const float4*)(wgt + (size_t)row * D);
    float4 a = r[lane];
    float4 b = r[lane + 32];
    float s = a.x * a.x;
    s = fmaf(a.y, a.y, s); s = fmaf(a.z, a.z, s); s = fmaf(a.w, a.w, s);
    s = fmaf(b.x, b.x, s); s = fmaf(b.y, b.y, s);
    s = fmaf(b.z, b.z, s); s = fmaf(b.w, b.w, s);
    #pragma unroll
    for (int o = 16; o > 0; o >>= 1) s += __shfl_xor_sync(0xffffffffu, s, o);
    if (lane == 0) g_wsq[row] = 0.5f * s;
}

// ---- fused: scores + argmax + gather + NCHW write + loss (incl. final reduce) ----
// argmin_k ||x-w_k||^2 == argmax_k (x.w_k - 0.5||w_k||^2).
// ST-estimator forward value == gathered codebook row.
// loss = codebook + 0.25*commit = 1.25 * mean((q-x)^2).
__global__ void __launch_bounds__(NTHREADS, 1)
vq_main(const float* __restrict__ inp, const float* __restrict__ wgt,
        float* __restrict__ out, int loss_index)
{
    extern __shared__ float smem[];
    float* Xs2   = smem;               // [128 dpairs][TP pos][2 dims] interleaved
    float* wbuf  = smem + 32768;       // 2 x [KC][D]
    float* wsq_s = smem + 32768 + 16384; // [K]

    const int tid = threadIdx.x;
    const int tp  = tid & 63;          // position pair: positions 2tp, 2tp+1
    const int tk  = tid >> 6;          // 0..3 -> codes tk*8 .. tk*8+7 (per chunk)

    const int n0  = blockIdx.x * TP;
    const int b   = n0 >> 10;          // image (TP divides HW=1024)
    const int hw0 = n0 & 1023;

    // prefetch W chunk 0 into registers (hidden under Xs2 fill)
    float4 frag[8];
    #pragma unroll
    for (int j = 0; j < 8; ++j) {
        int idx = tid + j * NTHREADS;
        int row = idx >> 6, c4 = (idx & 63) << 2;
        frag[j] = *(const float4*)(wgt + (size_t)row * D + c4);
    }
    #pragma unroll
    for (int j = 0; j < 4; ++j)
        wsq_s[tid + j * NTHREADS] = g_wsq[tid + j * NTHREADS];

    // fill Xs2: interleave dim pairs so one LDS.128 = 2 pos x 2 dims (= 2 f32x2 ops)
    {
        const float* src = inp + (((size_t)b * D) << 10) + hw0;
        #pragma unroll
        for (int it = 0; it < 16; ++it) {
            int idx = tid + it * NTHREADS;       // 0..4095 = (e, p-group)
            int e   = idx >> 5;                  // dim pair 0..127
            int p0  = (idx & 31) << 2;
            float4 xa = *(const float4*)(src + (((size_t)(2 * e    )) << 10) + p0);
            float4 xb = *(const float4*)(src + (((size_t)(2 * e + 1)) << 10) + p0);
            float2* row = (float2*)(Xs2 + e * (TP * 2));
            row[p0 + 0] = make_float2(xa.x, xb.x);
            row[p0 + 1] = make_float2(xa.y, xb.y);
            row[p0 + 2] = make_float2(xa.z, xb.z);
            row[p0 + 3] = make_float2(xa.w, xb.w);
        }
    }

    unsigned long long acc[2][8];
    #pragma unroll
    for (int pl = 0; pl < 2; ++pl)
        #pragma unroll
        for (int cc = 0; cc < 8; ++cc) acc[pl][cc] = 0ull;
    float bestv[2] = {-1e30f, -1e30f};
    int   besti[2] = {0, 0};

    for (int c = 0; c < NCHUNKS; ++c) {
        float* buf = wbuf + (c & 1) * (KC * D);
        // commit prefetched chunk (conflict-free STS.128)
        #pragma unroll
        for (int j = 0; j < 8; ++j) {
            int idx = tid + j * NTHREADS;
            int row = idx >> 6, c4 = (idx & 63) << 2;
            *(float4*)(buf + row * D + c4) = frag[j];
        }
        // prefetch next chunk (latency hidden under compute below)
        if (c + 1 < NCHUNKS) {
            #pragma unroll
            for (int j = 0; j < 8; ++j) {
                int idx = tid + j * NTHREADS;
                int row = idx >> 6, c4 = (idx & 63) << 2;
                frag[j] = *(const float4*)(wgt + (size_t)((c + 1) * KC + row) * D + c4);
            }
        }
        __syncthreads();   // buf ready (also: Xs2 ready on first iter)

        const float* wbase = buf + (tk * 8) * D;
        #pragma unroll 8
        for (int g = 0; g < 64; ++g) {          // g = float4 group of dims
            ulonglong2 x0 = *(const ulonglong2*)(Xs2 + (2 * g    ) * 256 + (tp << 2));
            ulonglong2 x1 = *(const ulonglong2*)(Xs2 + (2 * g + 1) * 256 + (tp << 2));
            #pragma unroll
            for (int cc = 0; cc < 8; ++cc) {
                ulonglong2 wv = *(const ulonglong2*)(wbase + cc * D + (g << 2));
                acc[0][cc] = ffma2(x0.x, wv.x, acc[0][cc]);
                acc[1][cc] = ffma2(x0.y, wv.x, acc[1][cc]);
                acc[0][cc] = ffma2(x1.x, wv.y, acc[0][cc]);
                acc[1][cc] = ffma2(x1.y, wv.y, acc[1][cc]);
            }
        }

        // chunk scores; ascending k with strict > => first (lowest) index wins
        const int kc = c * KC;
        #pragma unroll
        for (int cc = 0; cc < 8; ++cc) {
            int kidx = kc + tk * 8 + cc;
            float wh = wsq_s[kidx];
            #pragma unroll
            for (int pl = 0; pl < 2; ++pl) {
                float2 s2 = unpack2(acc[pl][cc]);
                acc[pl][cc] = 0ull;
                float s = s2.x + s2.y - wh;
                if (s > bestv[pl]) { bestv[pl] = s; besti[pl] = kidx; }
            }
        }
        __syncthreads();   // all done with buf before it is overwritten (c+2)
    }

    // ---- cross-thread argmax (4 tk-threads per position); alias wbuf ----
    float* redv = wbuf;                  // [TP][4]
    int*   redi = (int*)(wbuf + 512);    // [TP][4]
    int*   sidx = (int*)(wbuf + 1024);   // [TP]
    float* sred = wbuf + 1280;           // [NTHREADS]
    int*   sflg = (int*)(wbuf + 1536);

    #pragma unroll
    for (int pl = 0; pl < 2; ++pl) {
        int p = tp * 2 + pl;
        redv[p * 4 + tk] = bestv[pl];
        redi[p * 4 + tk] = besti[pl];
    }
    __syncthreads();
    if (tid < TP) {
        float bv = redv[tid * 4];
        int   bi = redi[tid * 4];
        #pragma unroll
        for (int t = 1; t < 4; ++t) {
            float v  = redv[tid * 4 + t];
            int   ti = redi[tid * 4 + t];
            if (v > bv || (v == bv && ti < bi)) { bv = v; bi = ti; }
        }
        sidx[tid] = bi;
    }
    __syncthreads();

    // ---- epilogue: vectorized gather + NCHW write + loss partial ----
    {
        int p  = tid & 127;
        int ds = tid >> 7;                 // splits the 64 float4-groups
        int myidx = sidx[p];
        const float4* wrow = (const float4*)(wgt + (size_t)myidx * D);
        float* op = out + (((size_t)b * D) << 10) + hw0 + p;
        float lsum = 0.f;
        #pragma unroll 4
        for (int i = 0; i < 32; ++i) {
            int g = ds + (i << 1);         // dims 4g..4g+3
            float4 q  = __ldg(wrow + g);
            float2 xa = *(const float2*)(Xs2 + (2 * g    ) * 256 + (p << 1));
            float2 xb = *(const float2*)(Xs2 + (2 * g + 1) * 256 + (p << 1));
            float d0 = q.x - xa.x, d1 = q.y - xa.y;
            float d2 = q.z - xb.x, d3 = q.w - xb.y;
            lsum = fmaf(d0, d0, lsum); lsum = fmaf(d1, d1, lsum);
            lsum = fmaf(d2, d2, lsum); lsum = fmaf(d3, d3, lsum);
            op[((size_t)(4 * g + 0)) << 10] = q.x;
            op[((size_t)(4 * g + 1)) << 10] = q.y;
            op[((size_t)(4 * g + 2)) << 10] = q.z;
            op[((size_t)(4 * g + 3)) << 10] = q.w;
        }
        sred[tid] = lsum;
        __syncthreads();
        #pragma unroll
        for (int s = NTHREADS / 2; s > 0; s >>= 1) {
            if (tid < s) sred[tid] += sred[tid + s];
            __syncthreads();
        }
        if (tid == 0) g_partial[blockIdx.x] = sred[0];
    }

    // ---- last-block loss finalize (deterministic; counter self-resets) ----
    if (tid == 0) {
        __threadfence();
        int t = atomicAdd(&g_count, 1);
        sflg[0] = (t == NBLOCKS - 1) ? 1 : 0;
    }
    __syncthreads();
    if (sflg[0]) {
        __threadfence();
        sred[tid] = g_partial[tid];        // NBLOCKS == NTHREADS == 256
        __syncthreads();
        #pragma unroll
        for (int s = NTHREADS / 2; s > 0; s >>= 1) {
            if (tid < s) sred[tid] += sred[tid + s];
            __syncthreads();
        }
        if (tid == 0) {
            out[loss_index] = 1.25f * sred[0] / (float)OUT_ELEMS;
            g_count = 0;
        }
    }
}

extern "C" void kernel_launch(void* const* d_in, const int* in_sizes, int n_in,
                              void* d_out, int out_size)
{
    (void)in_sizes; (void)n_in;
    const float* inp = (const float*)d_in[0];   // [32,256,32,32] fp32 NCHW
    const float* wgt = (const float*)d_in[1];   // [1024,256] fp32
    float* out = (float*)d_out;

    size_t smem_bytes = (size_t)SMEM_FLOATS * sizeof(float);   // 200704 B
    (void)cudaFuncSetAttribute(vq_main, cudaFuncAttributeMaxDynamicSharedMemorySize,
                               (int)smem_bytes);

    vq_wsq <<<K / 8, NTHREADS>>>(wgt);
    vq_main<<<NBLOCKS, NTHREADS, smem_bytes>>>(inp, wgt, out, out_size - 1);
}

// round 4
// speedup vs baseline: 1.6444x; 1.0365x over previous
#include <cuda_runtime.h>
#include <cstdint>
#include <cstddef>

#define D         256
#define K         1024
#define TP        128             // positions per block
#define KC        64              // codes per chunk
#define NCHUNKS   (K / KC)        // 16
#define NTHREADS  512
#define NBLOCKS   256             // 32768 / TP
#define OUT_ELEMS 8388608
#define WROW      264             // padded W row (floats); +4*th swizzle kills bank conflict

// smem floats: Xs2 (32768) + wbuf (KC*WROW = 16896) + wsq (1024) = 50688 -> 202752 B
#define SMEM_FLOATS (32768 + KC*WROW + 1024)

__device__ float g_wsq[K];
__device__ float g_partial[NBLOCKS];
__device__ int   g_count;         // zero-init; self-resets -> graph-replay safe

__device__ __forceinline__ unsigned long long ffma2(unsigned long long a,
                                                    unsigned long long b,
                                                    unsigned long long c) {
    unsigned long long d;
    asm("fma.rn.f32x2 %0, %1, %2, %3;" : "=l"(d) : "l"(a), "l"(b), "l"(c));
    return d;
}
__device__ __forceinline__ float2 unpack2(unsigned long long v) {
    float2 r;
    asm("mov.b64 {%0, %1}, %2;" : "=f"(r.x), "=f"(r.y) : "l"(v));
    return r;
}

// ---- 0.5*||w_k||^2 : warp per row ----
__global__ void vq_wsq(const float* __restrict__ wgt)
{
    int wid  = threadIdx.x >> 5;
    int lane = threadIdx.x & 31;
    int row  = blockIdx.x * 8 + wid;
    const float4* r = (const float4*)(wgt + (size_t)row * D);
    float4 a = r[lane];
    float4 b = r[lane + 32];
    float s = a.x * a.x;
    s = fmaf(a.y, a.y, s); s = fmaf(a.z, a.z, s); s = fmaf(a.w, a.w, s);
    s = fmaf(b.x, b.x, s); s = fmaf(b.y, b.y, s);
    s = fmaf(b.z, b.z, s); s = fmaf(b.w, b.w, s);
    #pragma unroll
    for (int o = 16; o > 0; o >>= 1) s += __shfl_xor_sync(0xffffffffu, s, o);
    if (lane == 0) g_wsq[row] = 0.5f * s;
}

// ---- fused: scores + argmax + gather + NCHW write + loss ----
// argmin_k ||x-w_k||^2 == argmax_k (x.w_k - 0.5||w_k||^2).
// ST-estimator forward value == gathered codebook row.
// loss = codebook + 0.25*commit = 1.25 * mean((q-x)^2).
__global__ void __launch_bounds__(NTHREADS, 1)
vq_main(const float* __restrict__ inp, const float* __restrict__ wgt,
        float* __restrict__ out, int loss_index)
{
    extern __shared__ float smem[];
    float* Xs2   = smem;                   // [128 dpairs][64 pos-pairs][2pos x 2dim]
    float* wbuf  = smem + 32768;           // [KC][WROW] (+4*th swizzle)
    float* wsq_s = smem + 32768 + KC*WROW; // [K]

    const int tid  = threadIdx.x;
    const int lane = tid & 31;
    const int warp = tid >> 5;
    const int pp   = (warp & 3) * 16 + (lane & 15);  // position pair 0..63
    const int th   = lane >> 4;                      // code half 0/1
    const int jrow = warp >> 2;                      // 0..3
    const int cbase = jrow * 16 + th * 8;            // first of this thread's 8 codes (in chunk)

    const int n0  = blockIdx.x * TP;
    const int b   = n0 >> 10;              // image (TP divides HW=1024)
    const int hw0 = n0 & 1023;

    // prefetch W chunk 0 into registers (hidden under Xs2 fill)
    float4 frag[8];
    #pragma unroll
    for (int j = 0; j < 8; ++j) {
        int idx = tid + j * NTHREADS;          // 0..4095 float4s
        int row = idx >> 6, c4 = (idx & 63) << 2;
        frag[j] = *(const float4*)(wgt + (size_t)row * D + c4);
    }
    #pragma unroll
    for (int j = 0; j < 2; ++j)
        wsq_s[tid + j * NTHREADS] = g_wsq[tid + j * NTHREADS];

    // fill Xs2: Xs2[e*256 + p*2 + {0,1}] = x[dim 2e / 2e+1][pos p]
    {
        const float* src = inp + (((size_t)b * D) << 10) + hw0;
        #pragma unroll
        for (int it = 0; it < 8; ++it) {
            int idx = tid + it * NTHREADS;     // 0..4095
            int e   = idx >> 5;                // dim pair 0..127
            int p0  = (idx & 31) << 2;
            float4 xa = *(const float4*)(src + (((size_t)(2 * e    )) << 10) + p0);
            float4 xb = *(const float4*)(src + (((size_t)(2 * e + 1)) << 10) + p0);
            float2* row = (float2*)(Xs2 + e * 256);
            row[p0 + 0] = make_float2(xa.x, xb.x);
            row[p0 + 1] = make_float2(xa.y, xb.y);
            row[p0 + 2] = make_float2(xa.z, xb.z);
            row[p0 + 3] = make_float2(xa.w, xb.w);
        }
    }

    unsigned long long acc[2][8];
    #pragma unroll
    for (int pl = 0; pl < 2; ++pl)
        #pragma unroll
        for (int cc = 0; cc < 8; ++cc) acc[pl][cc] = 0ull;
    float bestv[2] = {-1e30f, -1e30f};
    int   besti[2] = {0, 0};

    const float* xb2   = Xs2 + (pp << 2);
    const float* wbase = wbuf + cbase * WROW + 4 * th;   // swizzle: th halves differ by 4 floats

    for (int c = 0; c < NCHUNKS; ++c) {
        // commit prefetched chunk to smem (swizzled rows)
        #pragma unroll
        for (int j = 0; j < 8; ++j) {
            int idx = tid + j * NTHREADS;
            int row = idx >> 6, c4 = (idx & 63) << 2;
            *(float4*)(wbuf + row * WROW + 4 * ((row >> 3) & 1) + c4) = frag[j];
        }
        // prefetch next chunk (latency hidden under compute)
        if (c + 1 < NCHUNKS) {
            #pragma unroll
            for (int j = 0; j < 8; ++j) {
                int idx = tid + j * NTHREADS;
                int row = idx >> 6, c4 = (idx & 63) << 2;
                frag[j] = *(const float4*)(wgt + (size_t)((c + 1) * KC + row) * D + c4);
            }
        }
        __syncthreads();   // wbuf ready (first iter: also Xs2 ready)

        #pragma unroll 8
        for (int g = 0; g < 64; ++g) {           // g = 4-dim group (2 dpairs)
            ulonglong2 x0 = *(const ulonglong2*)(xb2 + (2 * g    ) * 256);
            ulonglong2 x1 = *(const ulonglong2*)(xb2 + (2 * g + 1) * 256);
            #pragma unroll
            for (int cc = 0; cc < 8; ++cc) {
                ulonglong2 wv = *(const ulonglong2*)(wbase + cc * WROW + (g << 2));
                acc[0][cc] = ffma2(x0.x, wv.x, acc[0][cc]);
                acc[1][cc] = ffma2(x0.y, wv.x, acc[1][cc]);
                acc[0][cc] = ffma2(x1.x, wv.y, acc[0][cc]);
                acc[1][cc] = ffma2(x1.y, wv.y, acc[1][cc]);
            }
        }

        // chunk scores; ascending k + strict > => lowest index wins
        const int kc = c * KC + cbase;
        #pragma unroll
        for (int cc = 0; cc < 8; ++cc) {
            float wh = wsq_s[kc + cc];
            #pragma unroll
            for (int pl = 0; pl < 2; ++pl) {
                float2 s2 = unpack2(acc[pl][cc]);
                acc[pl][cc] = 0ull;
                float s = s2.x + s2.y - wh;
                if (s > bestv[pl]) { bestv[pl] = s; besti[pl] = kc + cc; }
            }
        }
        __syncthreads();   // done with wbuf before next STS
    }

    // ---- cross-thread argmax (8 threads per position); alias wbuf ----
    float* redv = wbuf;                   // [TP][8]
    int*   redi = (int*)(wbuf + 1024);    // [TP][8]
    int*   sidx = (int*)(wbuf + 2048);    // [TP]
    float* sred = wbuf + 2304;            // [NTHREADS]
    int*   sflg = (int*)(wbuf + 2816);

    const int slot = jrow * 2 + th;
    #pragma unroll
    for (int pl = 0; pl < 2; ++pl) {
        int p = pp * 2 + pl;
        redv[p * 8 + slot] = bestv[pl];
        redi[p * 8 + slot] = besti[pl];
    }
    __syncthreads();
    if (tid < TP) {
        float bv = redv[tid * 8];
        int   bi = redi[tid * 8];
        #pragma unroll
        for (int t = 1; t < 8; ++t) {
            float v  = redv[tid * 8 + t];
            int   ti = redi[tid * 8 + t];
            if (v > bv || (v == bv && ti < bi)) { bv = v; bi = ti; }
        }
        sidx[tid] = bi;
    }
    __syncthreads();

    // ---- epilogue: vectorized gather + NCHW write + loss partial ----
    {
        int p  = tid & 127;
        int ds = tid >> 7;                 // 4-way split of 64 float4 dim-groups
        int myidx = sidx[p];
        const float4* wrow = (const float4*)(wgt + (size_t)myidx * D);
        float* op = out + (((size_t)b * D) << 10) + hw0 + p;
        float lsum = 0.f;
        #pragma unroll 4
        for (int i = 0; i < 16; ++i) {
            int g = ds + (i << 2);         // dims 4g..4g+3
            float4 q  = __ldg(wrow + g);
            float2 xa = *(const float2*)(Xs2 + (2 * g    ) * 256 + (p << 1));
            float2 xbv= *(const float2*)(Xs2 + (2 * g + 1) * 256 + (p << 1));
            float d0 = q.x - xa.x, d1 = q.y - xa.y;
            float d2 = q.z - xbv.x, d3 = q.w - xbv.y;
            lsum = fmaf(d0, d0, lsum); lsum = fmaf(d1, d1, lsum);
            lsum = fmaf(d2, d2, lsum); lsum = fmaf(d3, d3, lsum);
            op[((size_t)(4 * g + 0)) << 10] = q.x;
            op[((size_t)(4 * g + 1)) << 10] = q.y;
            op[((size_t)(4 * g + 2)) << 10] = q.z;
            op[((size_t)(4 * g + 3)) << 10] = q.w;
        }
        sred[tid] = lsum;
        __syncthreads();
        #pragma unroll
        for (int s = NTHREADS / 2; s > 0; s >>= 1) {
            if (tid < s) sred[tid] += sred[tid + s];
            __syncthreads();
        }
        if (tid == 0) g_partial[blockIdx.x] = sred[0];
    }

    // ---- last-block loss finalize (deterministic; counter self-resets) ----
    if (tid == 0) {
        __threadfence();
        int t = atomicAdd(&g_count, 1);
        sflg[0] = (t == NBLOCKS - 1) ? 1 : 0;
    }
    __syncthreads();
    if (sflg[0]) {
        __threadfence();
        sred[tid] = (tid < NBLOCKS) ? g_partial[tid] : 0.f;
        __syncthreads();
        #pragma unroll
        for (int s = NTHREADS / 2; s > 0; s >>= 1) {
            if (tid < s) sred[tid] += sred[tid + s];
            __syncthreads();
        }
        if (tid == 0) {
            out[loss_index] = 1.25f * sred[0] / (float)OUT_ELEMS;
            g_count = 0;
        }
    }
}

extern "C" void kernel_launch(void* const* d_in, const int* in_sizes, int n_in,
                              void* d_out, int out_size)
{
    (void)in_sizes; (void)n_in;
    const float* inp = (const float*)d_in[0];   // [32,256,32,32] fp32 NCHW
    const float* wgt = (const float*)d_in[1];   // [1024,256] fp32
    float* out = (float*)d_out;

    size_t smem_bytes = (size_t)SMEM_FLOATS * sizeof(float);   // 202752 B
    (void)cudaFuncSetAttribute(vq_main, cudaFuncAttributeMaxDynamicSharedMemorySize,
                               (int)smem_bytes);

    vq_wsq <<<K / 8, 256>>>(wgt);
    vq_main<<<NBLOCKS, NTHREADS, smem_bytes>>>(inp, wgt, out, out_size - 1);
}

// round 7
// speedup vs baseline: 4.1363x; 2.5154x over previous
#include <cuda_runtime.h>
#include <cuda_fp16.h>
#include <cstdint>
#include <cstddef>

#define D         256
#define K         1024
#define TP        128            // positions per CTA
#define NTHREADS  512
#define NBLOCKS   256
#define OUT_ELEMS 8388608
#define NNC       8              // N-chunks of 128 codes
#define NKC       4              // K-pieces of 64 dims
#define XROW      264            // X smem row (halfs), 528B
#define WROWH     72             // W smem row (halfs), 144B

// ---- smem byte layout ----
#define OFF_XH    0
#define OFF_XL    67584          // 128*264*2
#define OFF_WH    135168         // 128*72*2 = 18432
#define OFF_WL    153600
#define OFF_WSQ   172032         // 1024 f32
#define OFF_REDV  176128         // 128*4 f32
#define OFF_REDI  178176         // 128*4 i32
#define OFF_SIDX  180224         // 128 i32
#define OFF_SRED  180736         // 512 f32
#define OFF_SFLG  182784
#define SMEM_BYTES 182800
#define OFF_TBUF  OFF_WH         // 32x132 f32 transpose buffer (init-only, aliases W)

__device__ float          g_wsq[K];
__device__ unsigned short g_whi[K * D];
__device__ unsigned short g_wlo[K * D];
__device__ float          g_partial[NBLOCKS];
__device__ int            g_count;

__device__ __forceinline__ void mma16816(float* c, const uint32_t* a, const uint32_t* b) {
    asm volatile(
        "mma.sync.aligned.m16n8k16.row.col.f32.f16.f16.f32 "
        "{%0,%1,%2,%3}, {%4,%5,%6,%7}, {%8,%9}, {%0,%1,%2,%3};"
        : "+f"(c[0]), "+f"(c[1]), "+f"(c[2]), "+f"(c[3])
        : "r"(a[0]), "r"(a[1]), "r"(a[2]), "r"(a[3]), "r"(b[0]), "r"(b[1]));
}

// ---- 0.5*||w||^2 : warp per row ----
__global__ void vq_wsq(const float* __restrict__ wgt)
{
    int wid  = threadIdx.x >> 5;
    int lane = threadIdx.x & 31;
    int row  = blockIdx.x * 8 + wid;
    const float4* r = (const float4*)(wgt + (size_t)row * D);
    float4 a = r[lane];
    float4 b = r[lane + 32];
    float s = a.x * a.x;
    s = fmaf(a.y, a.y, s); s = fmaf(a.z, a.z, s); s = fmaf(a.w, a.w, s);
    s = fmaf(b.x, b.x, s); s = fmaf(b.y, b.y, s);
    s = fmaf(b.z, b.z, s); s = fmaf(b.w, b.w, s);
    #pragma unroll
    for (int o = 16; o > 0; o >>= 1) s += __shfl_xor_sync(0xffffffffu, s, o);
    if (lane == 0) g_wsq[row] = 0.5f * s;
}

// ---- split W into fp16 hi/lo (Dekker): w = hi + lo + O(2^-22) ----
__global__ void vq_splitw(const float* __restrict__ wgt)
{
    int i = blockIdx.x * blockDim.x + threadIdx.x;   // 262144
    float x = wgt[i];
    __half h = __float2half_rn(x);
    float l = x - __half2float(h);
    g_whi[i] = __half_as_ushort(h);
    g_wlo[i] = __half_as_ushort(__float2half_rn(l));
}

// ---- main: fp16 3-split mma.sync score GEMM + argmax + gather + loss ----
__global__ void __launch_bounds__(NTHREADS, 1)
vq_main(const float* __restrict__ inp, const float* __restrict__ wgt,
        float* __restrict__ out, int loss_index)
{
    extern __shared__ char smem[];
    unsigned short* Xh = (unsigned short*)(smem + OFF_XH);
    unsigned short* Xl = (unsigned short*)(smem + OFF_XL);
    unsigned short* Wh = (unsigned short*)(smem + OFF_WH);
    unsigned short* Wl = (unsigned short*)(smem + OFF_WL);
    const uint32_t* Xh32 = (const uint32_t*)Xh;
    const uint32_t* Xl32 = (const uint32_t*)Xl;
    const uint32_t* Wh32 = (const uint32_t*)Wh;
    const uint32_t* Wl32 = (const uint32_t*)Wl;
    float* wsq_s = (float*)(smem + OFF_WSQ);
    float* tbuf  = (float*)(smem + OFF_TBUF);

    const int tid  = threadIdx.x;
    const int lane = tid & 31;
    const int warp = tid >> 5;
    const int g    = lane >> 2;      // groupID 0..7
    const int t    = lane & 3;       // threadID-in-group
    const int wN   = warp & 3;       // N-group: 32 codes
    const int wM   = warp >> 2;      // M-group: 32 positions

    const int n0  = blockIdx.x * TP;
    const int b   = n0 >> 10;
    const int hw0 = n0 & 1023;
    const float* xin = inp + (((size_t)b * D) << 10) + hw0;   // x[d][p]

    wsq_s[tid]       = g_wsq[tid];
    wsq_s[tid + 512] = g_wsq[tid + 512];

    // prefetch W piece 0 (codes 0..127, dims 0..63) into regs
    uint4 fh[2], fl[2];
    #pragma unroll
    for (int j = 0; j < 2; ++j) {
        int idx = tid + j * NTHREADS;
        int code = idx >> 3, seg = idx & 7;
        fh[j] = *(const uint4*)(g_whi + (size_t)code * D + seg * 8);
        fl[j] = *(const uint4*)(g_wlo + (size_t)code * D + seg * 8);
    }

    // ---- X transpose + fp16 split, 8 slices of 32 dims ----
    for (int dc = 0; dc < 8; ++dc) {
        {
            int d  = tid >> 4;
            int p0 = (tid & 15) << 3;
            const float* src = xin + (((size_t)(dc * 32 + d)) << 10) + p0;
            float4 v0 = *(const float4*)(src);
            float4 v1 = *(const float4*)(src + 4);
            float* dst = tbuf + d * 132 + p0;
            dst[0]=v0.x; dst[1]=v0.y; dst[2]=v0.z; dst[3]=v0.w;
            dst[4]=v1.x; dst[5]=v1.y; dst[6]=v1.z; dst[7]=v1.w;
        }
        __syncthreads();
        {
            int p  = tid & 127;
            int dq = tid >> 7;
            uint32_t ph[4], pl[4];
            #pragma unroll
            for (int i = 0; i < 4; ++i) {
                float x0 = tbuf[(dq * 8 + 2 * i    ) * 132 + p];
                float x1 = tbuf[(dq * 8 + 2 * i + 1) * 132 + p];
                __half h0 = __float2half_rn(x0), h1 = __float2half_rn(x1);
                __half l0 = __float2half_rn(x0 - __half2float(h0));
                __half l1 = __float2half_rn(x1 - __half2float(h1));
                ph[i] = (uint32_t)__half_as_ushort(h0) | ((uint32_t)__half_as_ushort(h1) << 16);
                pl[i] = (uint32_t)__half_as_ushort(l0) | ((uint32_t)__half_as_ushort(l1) << 16);
            }
            int ho = p * XROW + dc * 32 + dq * 8;
            *(uint4*)(Xh + ho) = make_uint4(ph[0], ph[1], ph[2], ph[3]);
            *(uint4*)(Xl + ho) = make_uint4(pl[0], pl[1], pl[2], pl[3]);
        }
        __syncthreads();
    }

    float acc[2][4][4];
    #pragma unroll
    for (int mt = 0; mt < 2; ++mt)
        #pragma unroll
        for (int nt = 0; nt < 4; ++nt)
            #pragma unroll
            for (int j = 0; j < 4; ++j) acc[mt][nt][j] = 0.f;
    float bestv[4] = {-1e30f, -1e30f, -1e30f, -1e30f};
    int   besti[4] = {0, 0, 0, 0};

    // ---- main loop: 32 pieces = 8 nc x 4 kc ----
    for (int piece = 0; piece < NNC * NKC; ++piece) {
        const int nc = piece >> 2;
        const int kc = piece & 3;

        #pragma unroll
        for (int j = 0; j < 2; ++j) {
            int idx = tid + j * NTHREADS;
            int code = idx >> 3, seg = idx & 7;
            *(uint4*)(Wh + code * WROWH + seg * 8) = fh[j];
            *(uint4*)(Wl + code * WROWH + seg * 8) = fl[j];
        }
        if (piece + 1 < NNC * NKC) {
            int nn = (piece + 1) >> 2, nk = (piece + 1) & 3;
            #pragma unroll
            for (int j = 0; j < 2; ++j) {
                int idx = tid + j * NTHREADS;
                int code = idx >> 3, seg = idx & 7;
                size_t src = (size_t)(nn * 128 + code) * D + nk * 64 + seg * 8;
                fh[j] = *(const uint4*)(g_whi + src);
                fl[j] = *(const uint4*)(g_wlo + src);
            }
        }
        __syncthreads();

        #pragma unroll
        for (int ks = 0; ks < 4; ++ks) {
            uint32_t ah[2][4], al[2][4];
            #pragma unroll
            for (int mt = 0; mt < 2; ++mt) {
                int base = (wM * 32 + mt * 16 + g) * 132 + kc * 32 + ks * 8 + t;
                ah[mt][0] = Xh32[base];       ah[mt][1] = Xh32[base + 8 * 132];
                ah[mt][2] = Xh32[base + 4];   ah[mt][3] = Xh32[base + 8 * 132 + 4];
                al[mt][0] = Xl32[base];       al[mt][1] = Xl32[base + 8 * 132];
                al[mt][2] = Xl32[base + 4];   al[mt][3] = Xl32[base + 8 * 132 + 4];
            }
            uint32_t bh[4][2], bl[4][2];
            #pragma unroll
            for (int nt = 0; nt < 4; ++nt) {
                int bb = (wN * 32 + nt * 8 + g) * 36 + ks * 8 + t;
                bh[nt][0] = Wh32[bb]; bh[nt][1] = Wh32[bb + 4];
                bl[nt][0] = Wl32[bb]; bl[nt][1] = Wl32[bb + 4];
            }
            #pragma unroll
            for (int mt = 0; mt < 2; ++mt)
                #pragma unroll
                for (int nt = 0; nt < 4; ++nt) {
                    mma16816(acc[mt][nt], ah[mt], bh[nt]);
                    mma16816(acc[mt][nt], ah[mt], bl[nt]);
                    mma16816(acc[mt][nt], al[mt], bh[nt]);
                }
        }

        if (kc == 3) {
            #pragma unroll
            for (int nt = 0; nt < 4; ++nt)
                #pragma unroll
                for (int j = 0; j < 4; ++j) {
                    int n = nc * 128 + wN * 32 + nt * 8 + 2 * t + (j & 1);
                    float wh = wsq_s[n];
                    #pragma unroll
                    for (int mt = 0; mt < 2; ++mt) {
                        int slot = mt * 2 + (j >> 1);   // bit1=mt(+16), bit0=row+8
                        float s = acc[mt][nt][j] - wh;
                        if (s > bestv[slot]) { bestv[slot] = s; besti[slot] = n; }
                        acc[mt][nt][j] = 0.f;
                    }
                }
        }
        __syncthreads();
    }

    // ---- shfl reduce across t (lanes g*4..g*4+3 share positions) ----
    #pragma unroll
    for (int o = 1; o <= 2; o <<= 1) {
        #pragma unroll
        for (int s = 0; s < 4; ++s) {
            float ov = __shfl_xor_sync(0xffffffffu, bestv[s], o);
            int   oi = __shfl_xor_sync(0xffffffffu, besti[s], o);
            if (ov > bestv[s] || (ov == bestv[s] && oi < besti[s])) {
                bestv[s] = ov; besti[s] = oi;
            }
        }
    }
    float* redv = (float*)(smem + OFF_REDV);
    int*   redi = (int*)(smem + OFF_REDI);
    int*   sidx = (int*)(smem + OFF_SIDX);
    float* sred = (float*)(smem + OFF_SRED);
    int*   sflg = (int*)(smem + OFF_SFLG);
    if (t == 0) {
        #pragma unroll
        for (int s = 0; s < 4; ++s) {
            // FIX: slot bit1 = mt (+16 rows), bit0 = C-fragment row+8
            int p = wM * 32 + (s >> 1) * 16 + (s & 1) * 8 + g;
            redv[p * 4 + wN] = bestv[s];
            redi[p * 4 + wN] = besti[s];
        }
    }
    __syncthreads();
    if (tid < TP) {
        float bv = redv[tid * 4];
        int   bi = redi[tid * 4];
        #pragma unroll
        for (int q = 1; q < 4; ++q) {
            float v  = redv[tid * 4 + q];
            int   ti = redi[tid * 4 + q];
            if (v > bv || (v == bv && ti < bi)) { bv = v; bi = ti; }
        }
        sidx[tid] = bi;
    }
    __syncthreads();

    // ---- epilogue: gather + NCHW write + loss partial ----
    {
        int p  = tid & 127;
        int ds = tid >> 7;
        int myidx = sidx[p];
        const float4* wrow = (const float4*)(wgt + (size_t)myidx * D);
        float* op = out + (((size_t)b * D) << 10) + hw0 + p;
        const float* xp = xin + p;
        float lsum = 0.f;
        #pragma unroll 4
        for (int i = 0; i < 16; ++i) {
            int gq = ds + (i << 2);
            float4 q = __ldg(wrow + gq);
            float x0 = xp[((size_t)(4 * gq + 0)) << 10];
            float x1 = xp[((size_t)(4 * gq + 1)) << 10];
            float x2 = xp[((size_t)(4 * gq + 2)) << 10];
            float x3 = xp[((size_t)(4 * gq + 3)) << 10];
            float d0 = q.x - x0, d1 = q.y - x1, d2 = q.z - x2, d3 = q.w - x3;
            lsum = fmaf(d0, d0, lsum); lsum = fmaf(d1, d1, lsum);
            lsum = fmaf(d2, d2, lsum); lsum = fmaf(d3, d3, lsum);
            op[((size_t)(4 * gq + 0)) << 10] = q.x;
            op[((size_t)(4 * gq + 1)) << 10] = q.y;
            op[((size_t)(4 * gq + 2)) << 10] = q.z;
            op[((size_t)(4 * gq + 3)) << 10] = q.w;
        }
        sred[tid] = lsum;
    }
    __syncthreads();
    #pragma unroll
    for (int s = NTHREADS / 2; s > 0; s >>= 1) {
        if (tid < s) sred[tid] += sred[tid + s];
        __syncthreads();
    }
    if (tid == 0) g_partial[blockIdx.x] = sred[0];

    // ---- last-block loss finalize ----
    if (tid == 0) {
        __threadfence();
        int c = atomicAdd(&g_count, 1);
        sflg[0] = (c == NBLOCKS - 1) ? 1 : 0;
    }
    __syncthreads();
    if (sflg[0]) {
        __threadfence();
        sred[tid] = (tid < NBLOCKS) ? g_partial[tid] : 0.f;
        __syncthreads();
        #pragma unroll
        for (int s = NTHREADS / 2; s > 0; s >>= 1) {
            if (tid < s) sred[tid] += sred[tid + s];
            __syncthreads();
        }
        if (tid == 0) {
            out[loss_index] = 1.25f * sred[0] / (float)OUT_ELEMS;
            g_count = 0;
        }
    }
}

extern "C" void kernel_launch(void* const* d_in, const int* in_sizes, int n_in,
                              void* d_out, int out_size)
{
    (void)in_sizes; (void)n_in;
    const float* inp = (const float*)d_in[0];   // [32,256,32,32] fp32 NCHW
    const float* wgt = (const float*)d_in[1];   // [1024,256] fp32
    float* out = (float*)d_out;

    (void)cudaFuncSetAttribute(vq_main, cudaFuncAttributeMaxDynamicSharedMemorySize,
                               SMEM_BYTES);

    vq_wsq  <<<K / 8, 256>>>(wgt);
    vq_splitw<<<512, 512>>>(wgt);
    vq_main <<<NBLOCKS, NTHREADS, SMEM_BYTES>>>(inp, wgt, out, out_size - 1);
}

// round 8
// speedup vs baseline: 4.4463x; 1.0750x over previous
#include <cuda_runtime.h>
#include <cuda_fp16.h>
#include <cstdint>
#include <cstddef>

#define D         256
#define K         1024
#define TP        128
#define NTHREADS  512
#define NBLOCKS   256
#define OUT_ELEMS 8388608
#define XROW      264            // X smem row (halfs): 528B, 16B-granule stride 33 (==1 mod 8)
#define WROWH     72             // W smem row (halfs): 144B, granule stride 9 (==1 mod 8)

// ---- smem byte layout ----
#define OFF_XH    0              // 128*264*2 = 67584
#define OFF_XL    67584
#define OFF_WH0   135168         // 128*72*2 = 18432 per tile
#define OFF_WL0   153600
#define OFF_WH1   172032
#define OFF_WL1   190464
#define OFF_WSQ   208896         // 1024 f32
#define OFF_REDV  212992         // 128*4 f32
#define OFF_REDI  215040
#define OFF_SIDX  217088
#define OFF_SRED  217600         // 512 f32
#define OFF_SFLG  219648
#define SMEM_BYTES 219664
#define OFF_TBUF  OFF_WH0        // 32x132 f32 transpose buffer (X-fill phase only)

__device__ float          g_wsq[K];
__device__ unsigned short g_whi[K * D];
__device__ unsigned short g_wlo[K * D];
__device__ float          g_partial[NBLOCKS];
__device__ int            g_count;

__device__ __forceinline__ uint32_t smem_u32(const void* p) {
    uint32_t a;
    asm("{ .reg .u64 t; cvta.to.shared.u64 t, %1; cvt.u32.u64 %0, t; }" : "=r"(a) : "l"(p));
    return a;
}
__device__ __forceinline__ void ldsm4(uint32_t* r, uint32_t addr) {
    asm volatile("ldmatrix.sync.aligned.m8n8.x4.shared.b16 {%0,%1,%2,%3}, [%4];"
                 : "=r"(r[0]), "=r"(r[1]), "=r"(r[2]), "=r"(r[3]) : "r"(addr));
}
__device__ __forceinline__ void mma16816(float* c, const uint32_t* a, const uint32_t* b) {
    asm volatile(
        "mma.sync.aligned.m16n8k16.row.col.f32.f16.f16.f32 "
        "{%0,%1,%2,%3}, {%4,%5,%6,%7}, {%8,%9}, {%0,%1,%2,%3};"
        : "+f"(c[0]), "+f"(c[1]), "+f"(c[2]), "+f"(c[3])
        : "r"(a[0]), "r"(a[1]), "r"(a[2]), "r"(a[3]), "r"(b[0]), "r"(b[1]));
}

// ---- fused prep: 0.5*||w||^2 + Dekker fp16 split of W (warp per row) ----
__global__ void vq_prep(const float* __restrict__ wgt)
{
    int wid  = threadIdx.x >> 5;
    int lane = threadIdx.x & 31;
    int row  = blockIdx.x * 8 + wid;
    const float4* r = (const float4*)(wgt + (size_t)row * D);
    float4 a = r[lane];
    float4 b = r[lane + 32];
    float s = a.x * a.x;
    s = fmaf(a.y, a.y, s); s = fmaf(a.z, a.z, s); s = fmaf(a.w, a.w, s);
    s = fmaf(b.x, b.x, s); s = fmaf(b.y, b.y, s);
    s = fmaf(b.z, b.z, s); s = fmaf(b.w, b.w, s);
    #pragma unroll
    for (int o = 16; o > 0; o >>= 1) s += __shfl_xor_sync(0xffffffffu, s, o);
    if (lane == 0) g_wsq[row] = 0.5f * s;

    // split: dims lane*4..+3 and 128+lane*4..+3
    float v[2][4] = {{a.x, a.y, a.z, a.w}, {b.x, b.y, b.z, b.w}};
    #pragma unroll
    for (int h = 0; h < 2; ++h) {
        unsigned short ph[4], pl[4];
        #pragma unroll
        for (int i = 0; i < 4; ++i) {
            __half hi = __float2half_rn(v[h][i]);
            ph[i] = __half_as_ushort(hi);
            pl[i] = __half_as_ushort(__float2half_rn(v[h][i] - __half2float(hi)));
        }
        size_t off = (size_t)row * D + h * 128 + lane * 4;
        *(uint2*)(g_whi + off) = *(uint2*)ph;
        *(uint2*)(g_wlo + off) = *(uint2*)pl;
    }
}

// ---- main: fp16 3-split mma.sync score GEMM + argmax + gather + loss ----
__global__ void __launch_bounds__(NTHREADS, 1)
vq_main(const float* __restrict__ inp, const float* __restrict__ wgt,
        float* __restrict__ out, int loss_index)
{
    extern __shared__ char smem[];
    const uint32_t sb = smem_u32(smem);
    float* wsq_s = (float*)(smem + OFF_WSQ);
    float* tbuf  = (float*)(smem + OFF_TBUF);
    unsigned short* Xh = (unsigned short*)(smem + OFF_XH);
    unsigned short* Xl = (unsigned short*)(smem + OFF_XL);

    const int tid  = threadIdx.x;
    const int lane = tid & 31;
    const int warp = tid >> 5;
    const int g    = lane >> 2;
    const int t    = lane & 3;
    const int wN   = warp & 3;
    const int wM   = warp >> 2;
    const int mi   = lane >> 3;      // ldmatrix matrix id
    const int mr   = lane & 7;       // ldmatrix row-in-matrix

    const int n0  = blockIdx.x * TP;
    const int b   = n0 >> 10;
    const int hw0 = n0 & 1023;
    const float* xin = inp + (((size_t)b * D) << 10) + hw0;

    wsq_s[tid]       = g_wsq[tid];
    wsq_s[tid + 512] = g_wsq[tid + 512];

    // ldmatrix base addresses (bytes)
    uint32_t aXh[2], aXl[2], rB[2];
    #pragma unroll
    for (int mt = 0; mt < 2; ++mt) {
        uint32_t off = (uint32_t)((wM * 32 + mt * 16 + (mi & 1) * 8 + mr) * XROW
                                  + (mi >> 1) * 8) * 2;
        aXh[mt] = sb + OFF_XH + off;
        aXl[mt] = sb + OFF_XL + off;
    }
    #pragma unroll
    for (int q = 0; q < 2; ++q)
        rB[q] = (uint32_t)((wN * 32 + (q * 2 + (mi >> 1)) * 8 + mr) * WROWH
                           + (mi & 1) * 8) * 2;

    // prefetch W piece 0 into regs
    uint4 fh[2], fl[2];
    #pragma unroll
    for (int j = 0; j < 2; ++j) {
        int idx = tid + j * NTHREADS;
        int code = idx >> 3, seg = idx & 7;
        fh[j] = *(const uint4*)(g_whi + (size_t)code * D + seg * 8);
        fl[j] = *(const uint4*)(g_wlo + (size_t)code * D + seg * 8);
    }

    // ---- X transpose + fp16 split, 8 slices of 32 dims ----
    for (int dc = 0; dc < 8; ++dc) {
        {
            int d  = tid >> 4;
            int p0 = (tid & 15) << 3;
            const float* src = xin + (((size_t)(dc * 32 + d)) << 10) + p0;
            float4 v0 = *(const float4*)(src);
            float4 v1 = *(const float4*)(src + 4);
            float* dst = tbuf + d * 132 + p0;
            dst[0]=v0.x; dst[1]=v0.y; dst[2]=v0.z; dst[3]=v0.w;
            dst[4]=v1.x; dst[5]=v1.y; dst[6]=v1.z; dst[7]=v1.w;
        }
        __syncthreads();
        {
            int p  = tid & 127;
            int dq = tid >> 7;
            uint32_t ph[4], pl[4];
            #pragma unroll
            for (int i = 0; i < 4; ++i) {
                float x0 = tbuf[(dq * 8 + 2 * i    ) * 132 + p];
                float x1 = tbuf[(dq * 8 + 2 * i + 1) * 132 + p];
                __half h0 = __float2half_rn(x0), h1 = __float2half_rn(x1);
                __half l0 = __float2half_rn(x0 - __half2float(h0));
                __half l1 = __float2half_rn(x1 - __half2float(h1));
                ph[i] = (uint32_t)__half_as_ushort(h0) | ((uint32_t)__half_as_ushort(h1) << 16);
                pl[i] = (uint32_t)__half_as_ushort(l0) | ((uint32_t)__half_as_ushort(l1) << 16);
            }
            int ho = p * XROW + dc * 32 + dq * 8;
            *(uint4*)(Xh + ho) = make_uint4(ph[0], ph[1], ph[2], ph[3]);
            *(uint4*)(Xl + ho) = make_uint4(pl[0], pl[1], pl[2], pl[3]);
        }
        __syncthreads();
    }

    float acc[2][4][4];
    #pragma unroll
    for (int mt = 0; mt < 2; ++mt)
        #pragma unroll
        for (int nt = 0; nt < 4; ++nt)
            #pragma unroll
            for (int j = 0; j < 4; ++j) acc[mt][nt][j] = 0.f;
    float bestv[4] = {-1e30f, -1e30f, -1e30f, -1e30f};
    int   besti[4] = {0, 0, 0, 0};

    // ---- main loop: 32 pieces (8 nc x 4 kc), double-buffered W, 1 sync/piece ----
    for (int piece = 0; piece < 32; ++piece) {
        const int nc   = piece >> 2;
        const int kc   = piece & 3;
        const int bsel = piece & 1;
        unsigned short* WhB = (unsigned short*)(smem + (bsel ? OFF_WH1 : OFF_WH0));
        unsigned short* WlB = (unsigned short*)(smem + (bsel ? OFF_WL1 : OFF_WL0));

        // commit piece to its buffer
        #pragma unroll
        for (int j = 0; j < 2; ++j) {
            int idx = tid + j * NTHREADS;
            int code = idx >> 3, seg = idx & 7;
            *(uint4*)(WhB + code * WROWH + seg * 8) = fh[j];
            *(uint4*)(WlB + code * WROWH + seg * 8) = fl[j];
        }
        // prefetch next piece
        if (piece + 1 < 32) {
            int nn = (piece + 1) >> 2, nk = (piece + 1) & 3;
            #pragma unroll
            for (int j = 0; j < 2; ++j) {
                int idx = tid + j * NTHREADS;
                int code = idx >> 3, seg = idx & 7;
                size_t src = (size_t)(nn * 128 + code) * D + nk * 64 + seg * 8;
                fh[j] = *(const uint4*)(g_whi + src);
                fl[j] = *(const uint4*)(g_wlo + src);
            }
        }
        __syncthreads();   // buffer[bsel] ready; prior compute on it (piece-2) long done

        const uint32_t wbh = sb + (bsel ? OFF_WH1 : OFF_WH0);
        const uint32_t wbl = sb + (bsel ? OFF_WL1 : OFF_WL0);
        const uint32_t ao0 = (uint32_t)kc * 128;

        #pragma unroll
        for (int ks = 0; ks < 4; ++ks) {
            uint32_t ah0[4], ah1[4], al0[4], al1[4], bh[8], bl[8];
            uint32_t ao = ao0 + ks * 32;
            ldsm4(ah0, aXh[0] + ao);
            ldsm4(ah1, aXh[1] + ao);
            ldsm4(al0, aXl[0] + ao);
            ldsm4(al1, aXl[1] + ao);
            ldsm4(bh + 0, wbh + rB[0] + ks * 32);
            ldsm4(bh + 4, wbh + rB[1] + ks * 32);
            ldsm4(bl + 0, wbl + rB[0] + ks * 32);
            ldsm4(bl + 4, wbl + rB[1] + ks * 32);
            #pragma unroll
            for (int nt = 0; nt < 4; ++nt) {
                mma16816(acc[0][nt], ah0, &bh[nt * 2]);
                mma16816(acc[1][nt], ah1, &bh[nt * 2]);
                mma16816(acc[0][nt], ah0, &bl[nt * 2]);
                mma16816(acc[1][nt], ah1, &bl[nt * 2]);
                mma16816(acc[0][nt], al0, &bh[nt * 2]);
                mma16816(acc[1][nt], al1, &bh[nt * 2]);
            }
        }

        if (kc == 3) {
            #pragma unroll
            for (int nt = 0; nt < 4; ++nt)
                #pragma unroll
                for (int j = 0; j < 4; ++j) {
                    int n = nc * 128 + wN * 32 + nt * 8 + 2 * t + (j & 1);
                    float wh = wsq_s[n];
                    #pragma unroll
                    for (int mt = 0; mt < 2; ++mt) {
                        int slot = mt * 2 + (j >> 1);
                        float s = acc[mt][nt][j] - wh;
                        if (s > bestv[slot]) { bestv[slot] = s; besti[slot] = n; }
                        acc[mt][nt][j] = 0.f;
                    }
                }
        }
    }

    // ---- shfl reduce across t ----
    #pragma unroll
    for (int o = 1; o <= 2; o <<= 1) {
        #pragma unroll
        for (int s = 0; s < 4; ++s) {
            float ov = __shfl_xor_sync(0xffffffffu, bestv[s], o);
            int   oi = __shfl_xor_sync(0xffffffffu, besti[s], o);
            if (ov > bestv[s] || (ov == bestv[s] && oi < besti[s])) {
                bestv[s] = ov; besti[s] = oi;
            }
        }
    }
    float* redv = (float*)(smem + OFF_REDV);
    int*   redi = (int*)(smem + OFF_REDI);
    int*   sidx = (int*)(smem + OFF_SIDX);
    float* sred = (float*)(smem + OFF_SRED);
    int*   sflg = (int*)(smem + OFF_SFLG);
    __syncthreads();   // mainloop complete everywhere before aliasing W region
    if (t == 0) {
        #pragma unroll
        for (int s = 0; s < 4; ++s) {
            int p = wM * 32 + (s >> 1) * 16 + (s & 1) * 8 + g;
            redv[p * 4 + wN] = bestv[s];
            redi[p * 4 + wN] = besti[s];
        }
    }
    __syncthreads();
    if (tid < TP) {
        float bv = redv[tid * 4];
        int   bi = redi[tid * 4];
        #pragma unroll
        for (int q = 1; q < 4; ++q) {
            float v  = redv[tid * 4 + q];
            int   ti = redi[tid * 4 + q];
            if (v > bv || (v == bv && ti < bi)) { bv = v; bi = ti; }
        }
        sidx[tid] = bi;
    }
    __syncthreads();

    // ---- epilogue: gather + NCHW write + loss partial ----
    {
        int p  = tid & 127;
        int ds = tid >> 7;
        int myidx = sidx[p];
        const float4* wrow = (const float4*)(wgt + (size_t)myidx * D);
        float* op = out + (((size_t)b * D) << 10) + hw0 + p;
        const float* xp = xin + p;
        float lsum = 0.f;
        #pragma unroll 4
        for (int i = 0; i < 16; ++i) {
            int gq = ds + (i << 2);
            float4 q = __ldg(wrow + gq);
            float x0 = xp[((size_t)(4 * gq + 0)) << 10];
            float x1 = xp[((size_t)(4 * gq + 1)) << 10];
            float x2 = xp[((size_t)(4 * gq + 2)) << 10];
            float x3 = xp[((size_t)(4 * gq + 3)) << 10];
            float d0 = q.x - x0, d1 = q.y - x1, d2 = q.z - x2, d3 = q.w - x3;
            lsum = fmaf(d0, d0, lsum); lsum = fmaf(d1, d1, lsum);
            lsum = fmaf(d2, d2, lsum); lsum = fmaf(d3, d3, lsum);
            op[((size_t)(4 * gq + 0)) << 10] = q.x;
            op[((size_t)(4 * gq + 1)) << 10] = q.y;
            op[((size_t)(4 * gq + 2)) << 10] = q.z;
            op[((size_t)(4 * gq + 3)) << 10] = q.w;
        }
        sred[tid] = lsum;
    }
    __syncthreads();
    #pragma unroll
    for (int s = NTHREADS / 2; s > 0; s >>= 1) {
        if (tid < s) sred[tid] += sred[tid + s];
        __syncthreads();
    }
    if (tid == 0) g_partial[blockIdx.x] = sred[0];

    // ---- last-block loss finalize ----
    if (tid == 0) {
        __threadfence();
        int c = atomicAdd(&g_count, 1);
        sflg[0] = (c == NBLOCKS - 1) ? 1 : 0;
    }
    __syncthreads();
    if (sflg[0]) {
        __threadfence();
        sred[tid] = (tid < NBLOCKS) ? g_partial[tid] : 0.f;
        __syncthreads();
        #pragma unroll
        for (int s = NTHREADS / 2; s > 0; s >>= 1) {
            if (tid < s) sred[tid] += sred[tid + s];
            __syncthreads();
        }
        if (tid == 0) {
            out[loss_index] = 1.25f * sred[0] / (float)OUT_ELEMS;
            g_count = 0;
        }
    }
}

extern "C" void kernel_launch(void* const* d_in, const int* in_sizes, int n_in,
                              void* d_out, int out_size)
{
    (void)in_sizes; (void)n_in;
    const float* inp = (const float*)d_in[0];   // [32,256,32,32] fp32 NCHW
    const float* wgt = (const float*)d_in[1];   // [1024,256] fp32
    float* out = (float*)d_out;

    (void)cudaFuncSetAttribute(vq_main, cudaFuncAttributeMaxDynamicSharedMemorySize,
                               SMEM_BYTES);

    vq_prep<<<K / 8, 256>>>(wgt);
    vq_main<<<NBLOCKS, NTHREADS, SMEM_BYTES>>>(inp, wgt, out, out_size - 1);
}